// round 9
// baseline (speedup 1.0000x reference)
#include <cuda_runtime.h>
#include <cuda_fp16.h>
#include <stdint.h>

// Problem shape (fixed by the dataset)
#define B_ 16
#define T_ 51
#define P_ 2048
#define Q_ 2048

// Tiling
#define PC 32                     // p's per slab (== warp size: lane = pl for coalesced loads)
#define PSPLIT (P_ / PC)          // 64 partial slices
#define QT 256                    // q's per main block (1 per thread)
#define QSPLIT (Q_ / QT)          // 8
// Slab layout: per-p region of 105 granules (16B each). Row t occupies
// granules {2t, 2t+1} (b0..7, b8..15), XOR-swizzled: g' = g ^ ((g>>3)&7).
#define PGRAN 105
#define SLAB_B (PGRAN * 16)       // 1680 bytes per p
#define SLAB_TOTAL (PC * SLAB_B)  // 53760 bytes of dynamic smem -> 4 blocks/SM

#define BQ (B_ * Q_)              // 32768 outputs
#define RSLICE 4                  // reduce stage-A slices
#define RCHUNK (PSPLIT / RSLICE)  // 16 chunks per slice
#define PFD 4                     // weight/delay prefetch depth (~600 cyc cover)

// Static device scratch (no allocations allowed)
__device__ float g_partial[(size_t)PSPLIT * BQ];    // 8.4 MB
__device__ float g_partial2[(size_t)RSLICE * BQ];   // 0.5 MB

__device__ __forceinline__ __half2 uint_as_half2(unsigned u) {
    __half2 h;
    *reinterpret_cast<unsigned*>(&h) = u;
    return h;
}

__device__ __forceinline__ unsigned swz(unsigned g) {   // bijective within 105-granule region
    return g ^ ((g >> 3) & 7u);
}

// ---------------------------------------------------------------------------
// Main kernel: build fp16 slab [pl][t][b] in-block from buf (swizzled),
// then gather + half2-interpolate + fp32-accumulate. 4 blocks/SM (32 warps).
// ---------------------------------------------------------------------------
__global__ void __launch_bounds__(256, 4)
main_kernel(const float* __restrict__ buf,
            const float* __restrict__ weight,
            const float* __restrict__ delay) {
    extern __shared__ unsigned char smem[];
    const int qb = blockIdx.x;            // 0..QSPLIT-1
    const int pb = blockIdx.y;            // 0..PSPLIT-1
    const int q  = qb * QT + threadIdx.x;
    const int p0 = pb * PC;

    // ---- Phase 1: build fp16 slab directly from buf ----
    // lane = pl -> coalesced 128B LDG per (b,t). STS.128 at granule
    // lane*105 + swz(2t+o): superbank (lane + swz)&7 -> exact 4-way.
    {
        const int lane = threadIdx.x & 31;
        const int warp = threadIdx.x >> 5;
        for (int item = warp; item < T_ * 2; item += 8) {
            const int t = item >> 1;
            const int o = item & 1;
            const float* src = buf + (size_t)(8 * o) * T_ * P_ + (size_t)t * P_ + p0 + lane;
            unsigned u[4];
#pragma unroll
            for (int k = 0; k < 4; k++) {
                float lo = src[(size_t)(2 * k)     * T_ * P_];
                float hi = src[(size_t)(2 * k + 1) * T_ * P_];
                __half2 hh = __floats2half2_rn(lo, hi);
                u[k] = *reinterpret_cast<unsigned*>(&hh);
            }
            *reinterpret_cast<uint4*>(smem + (lane * PGRAN + swz(2u * t + o)) * 16) =
                make_uint4(u[0], u[1], u[2], u[3]);
        }
    }
    __syncthreads();

    // ---- Phase 2: gather + accumulate ----
    float acc[16];
#pragma unroll
    for (int b = 0; b < 16; b++) acc[b] = 0.0f;

    const float* wp = weight + (size_t)p0 * Q_ + q;
    const float* dp = delay  + (size_t)p0 * Q_ + q;

    // Rotating prefetch buffers, depth PFD (clamped tail: valid mem, unused vals)
    float wbuf[PFD], dbuf[PFD];
#pragma unroll
    for (int k = 0; k < PFD; k++) {
        int i = k < PC ? k : PC - 1;
        wbuf[k] = wp[(size_t)i * Q_];
        dbuf[k] = dp[(size_t)i * Q_];
    }

#pragma unroll 4
    for (int pl = 0; pl < PC; pl++) {
        float w = wbuf[pl & (PFD - 1)], draw = dbuf[pl & (PFD - 1)];
        int ip = pl + PFD < PC ? pl + PFD : PC - 1;
        wbuf[pl & (PFD - 1)] = wp[(size_t)ip * Q_];
        dbuf[pl & (PFD - 1)] = dp[(size_t)ip * Q_];

        // d = D_MAX * sigmoid(draw); s is continuous in d so fast-math flips are harmless
        float d   = 50.0f * __fdividef(1.0f, 1.0f + __expf(-draw));
        float fdf = floorf(d);
        int   df  = (int)fdf;
        if (df > 49) { df = 49; fdf = 49.0f; }   // d==50 edge: alpha -> 1, picks row 50
        float a  = d - fdf;
        float wa = w * a;
        float w1 = w - wa;                       // w * (1 - a)

        // Broadcast blended weights to half2 (1 cvt.rn.f16x2.f32 each)
        __half2 wah = __float2half2_rn(wa);
        __half2 w1h = __float2half2_rn(w1);

        const unsigned char* base = smem + pl * SLAB_B;
        unsigned g  = 2u * (unsigned)df;
        unsigned s0 = swz(g);                    // (df,   b0..7)
        unsigned s2 = swz(g + 2);                // (df+1, b0..7)
        // partner granules: even g -> swz(g+1) = swz(g)^1 exactly
        uint4 f0 = *reinterpret_cast<const uint4*>(base + s0 * 16);
        uint4 f1 = *reinterpret_cast<const uint4*>(base + (s0 ^ 1u) * 16);   // (df,   b8..15)
        uint4 c0 = *reinterpret_cast<const uint4*>(base + s2 * 16);
        uint4 c1 = *reinterpret_cast<const uint4*>(base + (s2 ^ 1u) * 16);   // (df+1, b8..15)

        // s = w1*f + wa*c in half2, convert s only, accumulate fp32
#define STEP(uf, uc, i0) {                                              \
        __half2 sh = __hfma2(w1h, uint_as_half2(uf),                    \
                             __hmul2(wah, uint_as_half2(uc)));          \
        float2 sf = __half22float2(sh);                                 \
        acc[i0]     += sf.x;                                            \
        acc[i0 + 1] += sf.y; }

        STEP(f0.x, c0.x, 0)  STEP(f0.y, c0.y, 2)
        STEP(f0.z, c0.z, 4)  STEP(f0.w, c0.w, 6)
        STEP(f1.x, c1.x, 8)  STEP(f1.y, c1.y, 10)
        STEP(f1.z, c1.z, 12) STEP(f1.w, c1.w, 14)
#undef STEP
    }

    // Write fp32 partials for this p-chunk (coalesced over q).
    float* part = g_partial + (size_t)pb * BQ + q;
#pragma unroll
    for (int b = 0; b < 16; b++) part[(size_t)b * Q_] = acc[b];
}

// ---------------------------------------------------------------------------
// Deterministic two-stage reduction of partials -> out [B, Q]
// ---------------------------------------------------------------------------
__global__ void reduceA_kernel() {
    int i = blockIdx.x * blockDim.x + threadIdx.x;   // 0 .. BQ-1
    const float* src = g_partial + (size_t)(blockIdx.y * RCHUNK) * BQ + i;
    float s = 0.0f;
#pragma unroll
    for (int k = 0; k < RCHUNK; k++) s += src[(size_t)k * BQ];
    g_partial2[(size_t)blockIdx.y * BQ + i] = s;
}

__global__ void reduceB_kernel(float* __restrict__ out) {
    int i = blockIdx.x * blockDim.x + threadIdx.x;   // 0 .. BQ-1
    float s = 0.0f;
#pragma unroll
    for (int c = 0; c < RSLICE; c++) s += g_partial2[(size_t)c * BQ + i];
    out[i] = s;
}

// ---------------------------------------------------------------------------
extern "C" void kernel_launch(void* const* d_in, const int* in_sizes, int n_in,
                              void* d_out, int out_size) {
    (void)in_sizes; (void)n_in; (void)out_size;
    const float* buf    = (const float*)d_in[0];
    const float* weight = (const float*)d_in[1];
    const float* delay  = (const float*)d_in[2];

    cudaFuncSetAttribute(main_kernel, cudaFuncAttributeMaxDynamicSharedMemorySize, SLAB_TOTAL);

    main_kernel<<<dim3(QSPLIT, PSPLIT), QT, SLAB_TOTAL>>>(buf, weight, delay);
    reduceA_kernel<<<dim3(BQ / 128, RSLICE), 128>>>();
    reduceB_kernel<<<BQ / 256, 256>>>((float*)d_out);
}